// round 9
// baseline (speedup 1.0000x reference)
#include <cuda_runtime.h>
#include <cuda_bf16.h>
#include <cuda_fp8.h>
#include <cstdint>

using bf16  = __nv_bfloat16;
using bf162 = __nv_bfloat162;

// Problem dims: B=8, L=2048, V=1024, D=1024, fp32.
#define BATCH 8
#define MDIM  2048
#define NDIM  1024
#define KDIM  1024

// ---------------------------------------------------------------------------
// Device scratch (allocation-free rule: __device__ globals)
// ---------------------------------------------------------------------------
__device__ float   g_scores[(size_t)BATCH * MDIM * NDIM];   // 64 MB
__device__ bf16    g_Hh [(size_t)BATCH * MDIM * KDIM];      // GEMM1 A hi/lo
__device__ bf16    g_Hl [(size_t)BATCH * MDIM * KDIM];
__device__ bf16    g_Vbh[(size_t)BATCH * NDIM * KDIM];      // GEMM1 B hi/lo
__device__ bf16    g_Vbl[(size_t)BATCH * NDIM * KDIM];
__device__ bf16    g_Ph [(size_t)BATCH * MDIM * KDIM];      // GEMM2 A main (bf16)
__device__ uint8_t g_P16 [(size_t)BATCH * MDIM * KDIM];     // e4m3(16*p)
__device__ uint8_t g_Pl13[(size_t)BATCH * MDIM * KDIM];     // e4m3(8192*(p-ph))
__device__ bf16    g_VTh[(size_t)BATCH * NDIM * KDIM];      // GEMM2 B main (bf16, VT)
__device__ uint8_t g_VT8 [(size_t)BATCH * NDIM * KDIM];     // e4m3(v)
__device__ uint8_t g_VTl9[(size_t)BATCH * NDIM * KDIM];     // e4m3(512*(v-vh))

// ---------------------------------------------------------------------------
// PTX helpers
// ---------------------------------------------------------------------------
__device__ __forceinline__ uint32_t smem_u32(const void* p) {
    uint32_t a;
    asm("{ .reg .u64 t; cvta.to.shared.u64 t, %1; cvt.u32.u64 %0, t; }" : "=r"(a) : "l"(p));
    return a;
}
#define CP16(dst, src) \
    asm volatile("cp.async.cg.shared.global [%0], [%1], 16;" :: "r"(dst), "l"(src))
#define CP_COMMIT() asm volatile("cp.async.commit_group;" ::: "memory")
#define CP_WAIT1()  asm volatile("cp.async.wait_group 1;"  ::: "memory")

#define LDSM4(R, addr) \
    asm volatile("ldmatrix.sync.aligned.m8n8.x4.shared.b16 {%0,%1,%2,%3}, [%4];" \
        : "=r"((R)[0]), "=r"((R)[1]), "=r"((R)[2]), "=r"((R)[3]) : "r"(addr))

__device__ __forceinline__ void mma_bf16(float* c, const uint32_t* a, const uint32_t* b) {
    asm volatile(
        "mma.sync.aligned.m16n8k16.row.col.f32.bf16.bf16.f32 "
        "{%0,%1,%2,%3}, {%4,%5,%6,%7}, {%8,%9}, {%0,%1,%2,%3};"
        : "+f"(c[0]), "+f"(c[1]), "+f"(c[2]), "+f"(c[3])
        : "r"(a[0]), "r"(a[1]), "r"(a[2]), "r"(a[3]), "r"(b[0]), "r"(b[1]));
}
__device__ __forceinline__ void mma_fp8(float* c, const uint32_t* a, const uint32_t* b) {
    asm volatile(
        "mma.sync.aligned.m16n8k32.row.col.f32.e4m3.e4m3.f32 "
        "{%0,%1,%2,%3}, {%4,%5,%6,%7}, {%8,%9}, {%0,%1,%2,%3};"
        : "+f"(c[0]), "+f"(c[1]), "+f"(c[2]), "+f"(c[3])
        : "r"(a[0]), "r"(a[1]), "r"(a[2]), "r"(a[3]), "r"(b[0]), "r"(b[1]));
}

__device__ __forceinline__ uint8_t f2e4m3(float x) {
    return (uint8_t)__nv_cvt_float_to_fp8(x, __NV_SATFINITE, __NV_E4M3);
}

// ---------------------------------------------------------------------------
// Split conversions
// ---------------------------------------------------------------------------
__global__ __launch_bounds__(256)
void convert_H(const float* __restrict__ X) {
    const size_t i = (size_t)blockIdx.x * 256 + threadIdx.x;   // 8-float group idx
    float4 v0 = ((const float4*)X)[2 * i];
    float4 v1 = ((const float4*)X)[2 * i + 1];

    const float f[8] = {v0.x, v0.y, v0.z, v0.w, v1.x, v1.y, v1.z, v1.w};
    uint32_t hw[4], lw[4];
    #pragma unroll
    for (int q = 0; q < 4; q++) {
        bf16 ha = __float2bfloat16(f[2*q]);
        bf16 hb = __float2bfloat16(f[2*q + 1]);
        bf16 la = __float2bfloat16(f[2*q]     - __bfloat162float(ha));
        bf16 lb = __float2bfloat16(f[2*q + 1] - __bfloat162float(hb));
        bf162 hp(ha, hb), lp(la, lb);
        hw[q] = *(uint32_t*)&hp;
        lw[q] = *(uint32_t*)&lp;
    }
    ((uint4*)g_Hh)[i] = make_uint4(hw[0], hw[1], hw[2], hw[3]);
    ((uint4*)g_Hl)[i] = make_uint4(lw[0], lw[1], lw[2], lw[3]);
}

// V: straight hi/lo bf16 (GEMM1 B), transposed bf16 hi + fp8 main/lo (GEMM2 B).
__global__ __launch_bounds__(1024)
void convert_V(const float* __restrict__ Vx) {
    __shared__ float tile[32][33];
    const int b = blockIdx.z;
    const size_t base = (size_t)b * NDIM * KDIM;
    const int x = blockIdx.x * 32 + threadIdx.x;
    const int y = blockIdx.y * 32 + threadIdx.y;

    float v = Vx[base + (size_t)y * 1024 + x];
    bf16 h = __float2bfloat16(v);
    bf16 l = __float2bfloat16(v - __bfloat162float(h));
    g_Vbh[base + (size_t)y * 1024 + x] = h;
    g_Vbl[base + (size_t)y * 1024 + x] = l;

    tile[threadIdx.y][threadIdx.x] = v;
    __syncthreads();

    const int xt = blockIdx.y * 32 + threadIdx.x;
    const int yt = blockIdx.x * 32 + threadIdx.y;
    float tv = tile[threadIdx.x][threadIdx.y];
    bf16 th = __float2bfloat16(tv);
    float thf = __bfloat162float(th);
    const size_t o = base + (size_t)yt * 1024 + xt;
    g_VTh[o]  = th;
    g_VT8[o]  = f2e4m3(tv);
    g_VTl9[o] = f2e4m3((tv - thf) * 512.0f);
}

// ---------------------------------------------------------------------------
// GEMM1: split-bf16 mma.sync (NT): g_scores = H @ V^T. Same as R8 (best).
// CTA 128x128, BK=64, 8 warps, 3-stage cp.async, XOR swizzle on 128B rows.
// ---------------------------------------------------------------------------
#define TILE_BYTES  16384                    // 128 rows * 128 B (bf16 BK=64)
#define STAGE_BYTES (4 * TILE_BYTES)         // 65536
#define NSTAGE      3
#define SMEM_BYTES  (NSTAGE * STAGE_BYTES)   // 196608

#define SWZ(row, ch) ((uint32_t)((row) * 128 + (((ch) ^ ((row) & 7)) << 4)))

__global__ void __launch_bounds__(256, 1)
gemm1_split()
{
    extern __shared__ char smem[];
    const uint32_t smb = smem_u32(smem);

    const int tid  = threadIdx.x;
    const int wid  = tid >> 5;
    const int lane = tid & 31;
    const int warp_m = wid >> 2;
    const int warp_n = wid & 3;

    const int b  = blockIdx.z;
    const int m0 = blockIdx.y * 128;
    const int n0 = blockIdx.x * 128;

    const bf16* Ahp = g_Hh  + (size_t)b * MDIM * KDIM + (size_t)m0 * KDIM;
    const bf16* Alp = g_Hl  + (size_t)b * MDIM * KDIM + (size_t)m0 * KDIM;
    const bf16* Bhp = g_Vbh + (size_t)b * NDIM * KDIM + (size_t)n0 * KDIM;
    const bf16* Blp = g_Vbl + (size_t)b * NDIM * KDIM + (size_t)n0 * KDIM;

    auto load_stage = [&](int s, int kt) {
        const int ke = kt * 64;
        const uint32_t sbase = smb + s * STAGE_BYTES;
        #pragma unroll
        for (int i = 0; i < 4; i++) {
            const int c   = tid + i * 256;
            const int row = c >> 3;
            const int ch  = c & 7;
            const uint32_t dst = sbase + SWZ(row, ch);
            const size_t  goff = (size_t)row * KDIM + ke + ch * 8;
            CP16(dst + 0 * TILE_BYTES, Ahp + goff);
            CP16(dst + 1 * TILE_BYTES, Alp + goff);
            CP16(dst + 2 * TILE_BYTES, Bhp + goff);
            CP16(dst + 3 * TILE_BYTES, Blp + goff);
        }
    };

    float acc[4][4][4];
    #pragma unroll
    for (int mi = 0; mi < 4; mi++)
        #pragma unroll
        for (int ni = 0; ni < 4; ni++)
            #pragma unroll
            for (int r = 0; r < 4; r++) acc[mi][ni][r] = 0.f;

    load_stage(0, 0); CP_COMMIT();
    load_stage(1, 1); CP_COMMIT();

    const int NKT = KDIM / 64;
    for (int kt = 0; kt < NKT; kt++) {
        CP_WAIT1();
        __syncthreads();
        if (kt + 2 < NKT) load_stage((kt + 2) % NSTAGE, kt + 2);
        CP_COMMIT();

        const uint32_t sb = smb + (kt % NSTAGE) * STAGE_BYTES;

        #pragma unroll
        for (int ks = 0; ks < 64; ks += 16) {
            const int kch = ks >> 3;
            uint32_t aF[2][4][4];
            const int arow = warp_m * 64 + (lane & 15);
            const int ach  = kch + (lane >> 4);
            #pragma unroll
            for (int mi = 0; mi < 4; mi++) {
                const uint32_t addr = sb + SWZ(arow + mi * 16, ach);
                LDSM4(aF[0][mi], addr + 0 * TILE_BYTES);
                LDSM4(aF[1][mi], addr + 1 * TILE_BYTES);
            }
            uint32_t bF[2][4][2];
            const int brow = warp_n * 32 + (lane & 7) + ((lane >> 4) & 1) * 8;
            const int bch  = kch + ((lane >> 3) & 1);
            #pragma unroll
            for (int np = 0; np < 2; np++) {
                const uint32_t addr = sb + 2 * TILE_BYTES + SWZ(brow + np * 16, bch);
                uint32_t r4[4];
                LDSM4(r4, addr);
                bF[0][np*2][0]   = r4[0]; bF[0][np*2][1]   = r4[1];
                bF[0][np*2+1][0] = r4[2]; bF[0][np*2+1][1] = r4[3];
                LDSM4(r4, addr + TILE_BYTES);
                bF[1][np*2][0]   = r4[0]; bF[1][np*2][1]   = r4[1];
                bF[1][np*2+1][0] = r4[2]; bF[1][np*2+1][1] = r4[3];
            }
            #pragma unroll
            for (int mi = 0; mi < 4; mi++)
                #pragma unroll
                for (int ni = 0; ni < 4; ni++)
                    mma_bf16(acc[mi][ni], aF[0][mi], bF[0][ni]);
            #pragma unroll
            for (int mi = 0; mi < 4; mi++)
                #pragma unroll
                for (int ni = 0; ni < 4; ni++)
                    mma_bf16(acc[mi][ni], aF[0][mi], bF[1][ni]);
            #pragma unroll
            for (int mi = 0; mi < 4; mi++)
                #pragma unroll
                for (int ni = 0; ni < 4; ni++)
                    mma_bf16(acc[mi][ni], aF[1][mi], bF[0][ni]);
        }
    }

    float* Cb = g_scores + (size_t)b * MDIM * NDIM;
    #pragma unroll
    for (int mi = 0; mi < 4; mi++) {
        const int r = m0 + warp_m * 64 + mi * 16 + (lane >> 2);
        #pragma unroll
        for (int ni = 0; ni < 4; ni++) {
            const int cc = n0 + warp_n * 32 + ni * 8 + (lane & 3) * 2;
            *(float2*)&Cb[(size_t)r       * NDIM + cc] = make_float2(acc[mi][ni][0], acc[mi][ni][1]);
            *(float2*)&Cb[(size_t)(r + 8) * NDIM + cc] = make_float2(acc[mi][ni][2], acc[mi][ni][3]);
        }
    }
}

// ---------------------------------------------------------------------------
// GEMM2: Out = P @ V (via VT). Main term bf16 (Ph*VTh), cross terms e4m3:
//   acc8 += P16*VTl9 + Pl13*VT8   (both scaled 2^13)
//   out = acc + acc8 / 8192
// Per K64: 64 bf16 MMAs + 64 fp8 MMAs (vs 192 bf16 in the 3-pass scheme).
// ---------------------------------------------------------------------------
#define FTILE_BYTES 8192                     // 128 rows * 64 B (fp8 BK=64)
#define S2_PH   0
#define S2_VTH  16384
#define S2_P16  32768
#define S2_PL   (S2_P16 + FTILE_BYTES)
#define S2_V8   (S2_PL  + FTILE_BYTES)
#define S2_VL   (S2_V8  + FTILE_BYTES)
#define STAGE2_BYTES 65536
#define SMEM2_BYTES  (NSTAGE * STAGE2_BYTES) // 196608

// fp8 tile swizzle: 64B rows, row-pairs share a 128B block
#define FSWZ(row, ch) ((uint32_t)((((row) >> 1) << 7) + \
    ((((((row) & 1) << 2)) | (((ch) ^ (((row) >> 1) & 3)) & 3)) << 4)))

__global__ void __launch_bounds__(256, 1)
gemm2_mixed(float* __restrict__ Out)
{
    extern __shared__ char smem[];
    const uint32_t smb = smem_u32(smem);

    const int tid  = threadIdx.x;
    const int wid  = tid >> 5;
    const int lane = tid & 31;
    const int warp_m = wid >> 2;
    const int warp_n = wid & 3;

    const int b  = blockIdx.z;
    const int m0 = blockIdx.y * 128;
    const int n0 = blockIdx.x * 128;

    const bf16*    Php = g_Ph   + (size_t)b * MDIM * KDIM + (size_t)m0 * KDIM;
    const bf16*    Vhp = g_VTh  + (size_t)b * NDIM * KDIM + (size_t)n0 * KDIM;
    const uint8_t* P16p = g_P16  + (size_t)b * MDIM * KDIM + (size_t)m0 * KDIM;
    const uint8_t* Plp  = g_Pl13 + (size_t)b * MDIM * KDIM + (size_t)m0 * KDIM;
    const uint8_t* V8p  = g_VT8  + (size_t)b * NDIM * KDIM + (size_t)n0 * KDIM;
    const uint8_t* Vlp  = g_VTl9 + (size_t)b * NDIM * KDIM + (size_t)n0 * KDIM;

    auto load_stage = [&](int s, int kt) {
        const int ke = kt * 64;
        const uint32_t sbase = smb + s * STAGE2_BYTES;
        #pragma unroll
        for (int i = 0; i < 4; i++) {                   // bf16 tiles: 1024 chunks each
            const int c   = tid + i * 256;
            const int row = c >> 3;
            const int ch  = c & 7;
            const uint32_t dst = sbase + SWZ(row, ch);
            const size_t  goff = (size_t)row * KDIM + ke + ch * 8;
            CP16(dst + S2_PH,  Php + goff);
            CP16(dst + S2_VTH, Vhp + goff);
        }
        #pragma unroll
        for (int i = 0; i < 2; i++) {                   // fp8 tiles: 512 chunks each
            const int c   = tid + i * 256;
            const int row = c >> 2;
            const int ch  = c & 3;
            const uint32_t dst = sbase + FSWZ(row, ch);
            const size_t  goff = (size_t)row * KDIM + ke + ch * 16;
            CP16(dst + S2_P16, P16p + goff);
            CP16(dst + S2_PL,  Plp  + goff);
            CP16(dst + S2_V8,  V8p  + goff);
            CP16(dst + S2_VL,  Vlp  + goff);
        }
    };

    float acc[4][4][4], acc8[4][4][4];
    #pragma unroll
    for (int mi = 0; mi < 4; mi++)
        #pragma unroll
        for (int ni = 0; ni < 4; ni++)
            #pragma unroll
            for (int r = 0; r < 4; r++) { acc[mi][ni][r] = 0.f; acc8[mi][ni][r] = 0.f; }

    load_stage(0, 0); CP_COMMIT();
    load_stage(1, 1); CP_COMMIT();

    const int NKT = KDIM / 64;
    for (int kt = 0; kt < NKT; kt++) {
        CP_WAIT1();
        __syncthreads();
        if (kt + 2 < NKT) load_stage((kt + 2) % NSTAGE, kt + 2);
        CP_COMMIT();

        const uint32_t sb = smb + (kt % NSTAGE) * STAGE2_BYTES;

        #pragma unroll
        for (int j = 0; j < 2; j++) {         // two k32 halves of the K64 tile
            // ---- bf16 main: two k16 sub-steps ----
            #pragma unroll
            for (int s = 0; s < 2; s++) {
                const int kch = j * 4 + s * 2;
                uint32_t aF[4][4];
                const int arow = warp_m * 64 + (lane & 15);
                const int ach  = kch + (lane >> 4);
                #pragma unroll
                for (int mi = 0; mi < 4; mi++)
                    LDSM4(aF[mi], sb + S2_PH + SWZ(arow + mi * 16, ach));
                uint32_t bF[4][2];
                const int brow = warp_n * 32 + (lane & 7) + ((lane >> 4) & 1) * 8;
                const int bch  = kch + ((lane >> 3) & 1);
                #pragma unroll
                for (int np = 0; np < 2; np++) {
                    uint32_t r4[4];
                    LDSM4(r4, sb + S2_VTH + SWZ(brow + np * 16, bch));
                    bF[np*2][0]   = r4[0]; bF[np*2][1]   = r4[1];
                    bF[np*2+1][0] = r4[2]; bF[np*2+1][1] = r4[3];
                }
                #pragma unroll
                for (int mi = 0; mi < 4; mi++)
                    #pragma unroll
                    for (int ni = 0; ni < 4; ni++)
                        mma_bf16(acc[mi][ni], aF[mi], bF[ni]);
            }

            // ---- fp8 cross terms (k32 per MMA) ----
            uint32_t bV8[4][2], bVl[4][2];
            {
                const int brow = warp_n * 32 + (lane & 7) + (lane >> 4) * 8;
                const int bch  = 2 * j + ((lane >> 3) & 1);
                #pragma unroll
                for (int np = 0; np < 2; np++) {
                    const uint32_t a8 = FSWZ(brow + np * 16, bch);
                    uint32_t r4[4];
                    LDSM4(r4, sb + S2_V8 + a8);
                    bV8[np*2][0]   = r4[0]; bV8[np*2][1]   = r4[1];
                    bV8[np*2+1][0] = r4[2]; bV8[np*2+1][1] = r4[3];
                    LDSM4(r4, sb + S2_VL + a8);
                    bVl[np*2][0]   = r4[0]; bVl[np*2][1]   = r4[1];
                    bVl[np*2+1][0] = r4[2]; bVl[np*2+1][1] = r4[3];
                }
            }
            const int farow = (lane & 7) + ((lane >> 3) & 1) * 8;
            const int fach  = 2 * j + (lane >> 4);
            #pragma unroll
            for (int mi = 0; mi < 4; mi++) {
                uint32_t aP[4], aL[4];
                const int row = warp_m * 64 + mi * 16 + farow;
                LDSM4(aP, sb + S2_P16 + FSWZ(row, fach));
                LDSM4(aL, sb + S2_PL  + FSWZ(row, fach));
                #pragma unroll
                for (int ni = 0; ni < 4; ni++) {
                    mma_fp8(acc8[mi][ni], aP, bVl[ni]);   // P16 * VTl9
                    mma_fp8(acc8[mi][ni], aL, bV8[ni]);   // Pl13 * VT8
                }
            }
        }
    }

    // ---- epilogue: combine and store ----
    const float s8 = 1.0f / 8192.0f;
    float* Cb = Out + (size_t)b * MDIM * NDIM;
    #pragma unroll
    for (int mi = 0; mi < 4; mi++) {
        const int r = m0 + warp_m * 64 + mi * 16 + (lane >> 2);
        #pragma unroll
        for (int ni = 0; ni < 4; ni++) {
            const int cc = n0 + warp_n * 32 + ni * 8 + (lane & 3) * 2;
            float2 lo = make_float2(acc[mi][ni][0] + acc8[mi][ni][0] * s8,
                                    acc[mi][ni][1] + acc8[mi][ni][1] * s8);
            float2 hi = make_float2(acc[mi][ni][2] + acc8[mi][ni][2] * s8,
                                    acc[mi][ni][3] + acc8[mi][ni][3] * s8);
            *(float2*)&Cb[(size_t)r       * NDIM + cc] = lo;
            *(float2*)&Cb[(size_t)(r + 8) * NDIM + cc] = hi;
        }
    }
}

// ---------------------------------------------------------------------------
// Softmax over rows of g_scores; emits Ph (bf16) + P16/Pl13 (e4m3).
// ---------------------------------------------------------------------------
__global__ __launch_bounds__(256)
void softmax_split()
{
    const float* p = g_scores + (size_t)blockIdx.x * NDIM;
    const int tid  = threadIdx.x;
    const int lane = tid & 31;
    const int wid  = tid >> 5;

    __shared__ float red_max[8];
    __shared__ float red_sum[8];

    float4 v = ((const float4*)p)[tid];

    float m = fmaxf(fmaxf(v.x, v.y), fmaxf(v.z, v.w));
    #pragma unroll
    for (int o = 16; o > 0; o >>= 1) m = fmaxf(m, __shfl_xor_sync(0xFFFFFFFFu, m, o));
    if (lane == 0) red_max[wid] = m;
    __syncthreads();
    float bmax = red_max[0];
    #pragma unroll
    for (int i = 1; i < 8; i++) bmax = fmaxf(bmax, red_max[i]);

    v.x = __expf(v.x - bmax);
    v.y = __expf(v.y - bmax);
    v.z = __expf(v.z - bmax);
    v.w = __expf(v.w - bmax);

    float s = v.x + v.y + v.z + v.w;
    #pragma unroll
    for (int o = 16; o > 0; o >>= 1) s += __shfl_xor_sync(0xFFFFFFFFu, s, o);
    if (lane == 0) red_sum[wid] = s;
    __syncthreads();
    float tot = 0.f;
    #pragma unroll
    for (int i = 0; i < 8; i++) tot += red_sum[i];
    const float inv = __frcp_rn(tot);

    float pv[4] = {v.x * inv, v.y * inv, v.z * inv, v.w * inv};

    uint32_t hw[2], p16w = 0, plw = 0;
    bf16 h[4];
    #pragma unroll
    for (int q = 0; q < 4; q++) h[q] = __float2bfloat16(pv[q]);
    bf162 hp0(h[0], h[1]), hp1(h[2], h[3]);
    hw[0] = *(uint32_t*)&hp0; hw[1] = *(uint32_t*)&hp1;
    #pragma unroll
    for (int q = 0; q < 4; q++) {
        p16w |= (uint32_t)f2e4m3(pv[q] * 16.0f) << (8 * q);
        float pl = pv[q] - __bfloat162float(h[q]);
        plw  |= (uint32_t)f2e4m3(pl * 8192.0f) << (8 * q);
    }

    const size_t i4 = (size_t)blockIdx.x * (NDIM / 4) + tid;
    ((uint2*)g_Ph)[i4]      = make_uint2(hw[0], hw[1]);
    ((uint32_t*)g_P16)[i4]  = p16w;
    ((uint32_t*)g_Pl13)[i4] = plw;
}

// ---------------------------------------------------------------------------
extern "C" void kernel_launch(void* const* d_in, const int* in_sizes, int n_in,
                              void* d_out, int out_size)
{
    const float* H  = (const float*)d_in[0];   // (8, 2048, 1024)
    const float* Vx = (const float*)d_in[1];   // (8, 1024, 1024)
    float*       O  = (float*)d_out;           // (8, 2048, 1024)

    cudaFuncSetAttribute(gemm1_split, cudaFuncAttributeMaxDynamicSharedMemorySize, SMEM_BYTES);
    cudaFuncSetAttribute(gemm2_mixed, cudaFuncAttributeMaxDynamicSharedMemorySize, SMEM2_BYTES);

    convert_H<<<(BATCH * MDIM * KDIM) / 8 / 256, 256>>>(H);
    convert_V<<<dim3(32, 32, BATCH), dim3(32, 32)>>>(Vx);

    dim3 g(NDIM / 128, MDIM / 128, BATCH);       // (8, 16, 8)
    gemm1_split<<<g, 256, SMEM_BYTES>>>();       // scores = H @ V^T

    softmax_split<<<BATCH * MDIM, 256>>>();      // P -> Ph, P16, Pl13

    gemm2_mixed<<<g, 256, SMEM2_BYTES>>>(O);     // out = P @ V (bf16 + fp8 cross)
}

// round 11
// speedup vs baseline: 1.1404x; 1.1404x over previous
#include <cuda_runtime.h>
#include <cuda_bf16.h>
#include <cstdint>

using bf16  = __nv_bfloat16;
using bf162 = __nv_bfloat162;

// Problem dims: B=8, L=2048, V=1024, D=1024, fp32.
// Both GEMMs: M=2048, N=1024, K=1024 per batch, NT form (both operands K-major).
#define BATCH 8
#define MDIM  2048
#define NDIM  1024
#define KDIM  1024

// ---------------------------------------------------------------------------
// Device scratch (allocation-free rule: __device__ globals)
// ---------------------------------------------------------------------------
__device__ float g_scores[(size_t)BATCH * MDIM * NDIM];   // 64 MB
__device__ bf16  g_Hh [(size_t)BATCH * MDIM * KDIM];      // 32 MB each
__device__ bf16  g_Hl [(size_t)BATCH * MDIM * KDIM];
__device__ bf16  g_Ph [(size_t)BATCH * MDIM * KDIM];
__device__ bf16  g_Pl [(size_t)BATCH * MDIM * KDIM];
__device__ bf16  g_Vbh[(size_t)BATCH * NDIM * KDIM];      // 16 MB each
__device__ bf16  g_Vbl[(size_t)BATCH * NDIM * KDIM];
__device__ bf16  g_VTh[(size_t)BATCH * NDIM * KDIM];      // V transposed
__device__ bf16  g_VTl[(size_t)BATCH * NDIM * KDIM];

// ---------------------------------------------------------------------------
// PTX helpers (baseline sm_80+ features: cp.async, ldmatrix, mma.sync)
// ---------------------------------------------------------------------------
__device__ __forceinline__ uint32_t smem_u32(const void* p) {
    uint32_t a;
    asm("{ .reg .u64 t; cvta.to.shared.u64 t, %1; cvt.u32.u64 %0, t; }" : "=r"(a) : "l"(p));
    return a;
}
#define CP16(dst, src) \
    asm volatile("cp.async.cg.shared.global [%0], [%1], 16;" :: "r"(dst), "l"(src))
#define CP_COMMIT() asm volatile("cp.async.commit_group;" ::: "memory")
#define CP_WAIT1()  asm volatile("cp.async.wait_group 1;"  ::: "memory")

#define LDSM4(R, addr) \
    asm volatile("ldmatrix.sync.aligned.m8n8.x4.shared.b16 {%0,%1,%2,%3}, [%4];" \
        : "=r"((R)[0]), "=r"((R)[1]), "=r"((R)[2]), "=r"((R)[3]) : "r"(addr))

__device__ __forceinline__ void mma_bf16(float* c, const uint32_t* a, const uint32_t* b) {
    asm volatile(
        "mma.sync.aligned.m16n8k16.row.col.f32.bf16.bf16.f32 "
        "{%0,%1,%2,%3}, {%4,%5,%6,%7}, {%8,%9}, {%0,%1,%2,%3};"
        : "+f"(c[0]), "+f"(c[1]), "+f"(c[2]), "+f"(c[3])
        : "r"(a[0]), "r"(a[1]), "r"(a[2]), "r"(a[3]), "r"(b[0]), "r"(b[1]));
}

// ---------------------------------------------------------------------------
// Merged split-conversion kernel.
// Blocks [0, 8192): V path — per-batch 32x32 transpose tiles, emits
//   Vbh/Vbl (straight) and VTh/VTl (transposed).
// Blocks [8192, 10240): H path — 8 floats/thread, emits Hh/Hl as 16B stores.
// ---------------------------------------------------------------------------
#define V_BLOCKS 8192                          // 8 batches * 32 * 32
#define H_BLOCKS 2048                          // 16.78M floats / (1024 thr * 8)

__global__ __launch_bounds__(1024)
void convert_all(const float* __restrict__ H, const float* __restrict__ Vx)
{
    const int bid = blockIdx.x;
    if (bid < V_BLOCKS) {
        // ---- V path (1024 threads as 32x32) ----
        __shared__ float tile[32][33];
        const int b   = bid >> 10;              // /1024
        const int rem = bid & 1023;
        const int by  = rem >> 5;
        const int bx  = rem & 31;
        const int tx  = threadIdx.x & 31;
        const int ty  = threadIdx.x >> 5;
        const size_t base = (size_t)b * NDIM * KDIM;

        const int x = bx * 32 + tx;
        const int y = by * 32 + ty;
        float v = Vx[base + (size_t)y * 1024 + x];
        bf16 h = __float2bfloat16(v);
        bf16 l = __float2bfloat16(v - __bfloat162float(h));
        g_Vbh[base + (size_t)y * 1024 + x] = h;
        g_Vbl[base + (size_t)y * 1024 + x] = l;

        tile[ty][tx] = v;
        __syncthreads();

        const int xt = by * 32 + tx;
        const int yt = bx * 32 + ty;
        float tv = tile[tx][ty];
        bf16 th = __float2bfloat16(tv);
        bf16 tl = __float2bfloat16(tv - __bfloat162float(th));
        g_VTh[base + (size_t)yt * 1024 + xt] = th;
        g_VTl[base + (size_t)yt * 1024 + xt] = tl;
    } else {
        // ---- H path: 8 floats per thread ----
        const size_t i = (size_t)(bid - V_BLOCKS) * 1024 + threadIdx.x;  // 8-float group
        float4 v0 = ((const float4*)H)[2 * i];
        float4 v1 = ((const float4*)H)[2 * i + 1];
        const float f[8] = {v0.x, v0.y, v0.z, v0.w, v1.x, v1.y, v1.z, v1.w};
        uint32_t hw[4], lw[4];
        #pragma unroll
        for (int q = 0; q < 4; q++) {
            bf16 ha = __float2bfloat16(f[2*q]);
            bf16 hb = __float2bfloat16(f[2*q + 1]);
            bf16 la = __float2bfloat16(f[2*q]     - __bfloat162float(ha));
            bf16 lb = __float2bfloat16(f[2*q + 1] - __bfloat162float(hb));
            bf162 hp(ha, hb), lp(la, lb);
            hw[q] = *(uint32_t*)&hp;
            lw[q] = *(uint32_t*)&lp;
        }
        ((uint4*)g_Hh)[i] = make_uint4(hw[0], hw[1], hw[2], hw[3]);
        ((uint4*)g_Hl)[i] = make_uint4(lw[0], lw[1], lw[2], lw[3]);
    }
}

// ---------------------------------------------------------------------------
// Split-bf16 mma.sync GEMM (NT): C[m,n] = sum_k A[m,k]*B[n,k]
// CTA tile 128x128, BK=64, 8 warps (2 in M x 4 in N), warp tile 64x32.
// 3-stage cp.async pipeline, XOR-swizzled smem (128B rows, 16B atoms).
// ---------------------------------------------------------------------------
#define TILE_BYTES  16384                    // 128 rows * 128 B
#define STAGE_BYTES (4 * TILE_BYTES)         // 65536
#define NSTAGE      3
#define SMEM_BYTES  (NSTAGE * STAGE_BYTES)   // 196608

// byte offset of 16B atom (row, chunk) inside a tile, XOR swizzled
#define SWZ(row, ch) ((uint32_t)((row) * 128 + (((ch) ^ ((row) & 7)) << 4)))

__global__ void __launch_bounds__(256, 1)
gemm_split(int mode, float* __restrict__ Out)
{
    extern __shared__ char smem[];
    const uint32_t smb = smem_u32(smem);

    const int tid  = threadIdx.x;
    const int wid  = tid >> 5;
    const int lane = tid & 31;
    const int warp_m = wid >> 2;     // 0..1
    const int warp_n = wid & 3;      // 0..3

    const int b  = blockIdx.z;
    const int m0 = blockIdx.y * 128;
    const int n0 = blockIdx.x * 128;

    const bf16 *Ah, *Al, *Bh, *Bl;
    float* C;
    if (mode == 0) { Ah = g_Hh; Al = g_Hl; Bh = g_Vbh; Bl = g_Vbl; C = g_scores; }
    else           { Ah = g_Ph; Al = g_Pl; Bh = g_VTh; Bl = g_VTl; C = Out;      }

    const bf16* Ahp = Ah + (size_t)b * MDIM * KDIM + (size_t)m0 * KDIM;
    const bf16* Alp = Al + (size_t)b * MDIM * KDIM + (size_t)m0 * KDIM;
    const bf16* Bhp = Bh + (size_t)b * NDIM * KDIM + (size_t)n0 * KDIM;
    const bf16* Blp = Bl + (size_t)b * NDIM * KDIM + (size_t)n0 * KDIM;

    // ---- async stage loader: 4 tiles x (128 rows x 8 chunks of 16B) ----
    auto load_stage = [&](int s, int kt) {
        const int ke = kt * 64;
        const uint32_t sbase = smb + s * STAGE_BYTES;
        #pragma unroll
        for (int i = 0; i < 4; i++) {
            const int c   = tid + i * 256;    // 0..1023
            const int row = c >> 3;           // 0..127
            const int ch  = c & 7;            // 16B chunk within 128B row
            const uint32_t dst = sbase + SWZ(row, ch);
            const size_t  goff = (size_t)row * KDIM + ke + ch * 8;
            CP16(dst + 0 * TILE_BYTES, Ahp + goff);
            CP16(dst + 1 * TILE_BYTES, Alp + goff);
            CP16(dst + 2 * TILE_BYTES, Bhp + goff);
            CP16(dst + 3 * TILE_BYTES, Blp + goff);
        }
    };

    float acc[4][4][4];
    #pragma unroll
    for (int mi = 0; mi < 4; mi++)
        #pragma unroll
        for (int ni = 0; ni < 4; ni++)
            #pragma unroll
            for (int r = 0; r < 4; r++) acc[mi][ni][r] = 0.f;

    load_stage(0, 0); CP_COMMIT();
    load_stage(1, 1); CP_COMMIT();

    const int NKT = KDIM / 64;  // 16
    for (int kt = 0; kt < NKT; kt++) {
        CP_WAIT1();              // stage kt's group complete (<=1 pending)
        __syncthreads();         // all warps done reading stage (kt+2)%3

        // issue next stage's loads first — overlap with this stage's compute
        if (kt + 2 < NKT) load_stage((kt + 2) % NSTAGE, kt + 2);
        CP_COMMIT();

        const uint32_t sb = smb + (kt % NSTAGE) * STAGE_BYTES;

        #pragma unroll
        for (int ks = 0; ks < 64; ks += 16) {
            const int kch = ks >> 3;          // base chunk (2 chunks per k16)
            // A fragments (hi and lo), 4 m-tiles of 16
            uint32_t aF[2][4][4];
            const int arow = warp_m * 64 + (lane & 15);
            const int ach  = kch + (lane >> 4);
            #pragma unroll
            for (int mi = 0; mi < 4; mi++) {
                const uint32_t addr = sb + SWZ(arow + mi * 16, ach);
                LDSM4(aF[0][mi], addr + 0 * TILE_BYTES);
                LDSM4(aF[1][mi], addr + 1 * TILE_BYTES);
            }
            // B fragments (hi and lo), 4 n-tiles of 8 (as 2 x4 pairs)
            uint32_t bF[2][4][2];
            const int brow = warp_n * 32 + (lane & 7) + ((lane >> 4) & 1) * 8;
            const int bch  = kch + ((lane >> 3) & 1);
            #pragma unroll
            for (int np = 0; np < 2; np++) {
                const uint32_t addr = sb + 2 * TILE_BYTES + SWZ(brow + np * 16, bch);
                uint32_t r4[4];
                LDSM4(r4, addr);
                bF[0][np*2][0]   = r4[0]; bF[0][np*2][1]   = r4[1];
                bF[0][np*2+1][0] = r4[2]; bF[0][np*2+1][1] = r4[3];
                LDSM4(r4, addr + TILE_BYTES);
                bF[1][np*2][0]   = r4[0]; bF[1][np*2][1]   = r4[1];
                bF[1][np*2+1][0] = r4[2]; bF[1][np*2+1][1] = r4[3];
            }
            // 3 split passes, each a full sweep over the 16 (mi,ni) tiles
            #pragma unroll
            for (int mi = 0; mi < 4; mi++)
                #pragma unroll
                for (int ni = 0; ni < 4; ni++)
                    mma_bf16(acc[mi][ni], aF[0][mi], bF[0][ni]);
            #pragma unroll
            for (int mi = 0; mi < 4; mi++)
                #pragma unroll
                for (int ni = 0; ni < 4; ni++)
                    mma_bf16(acc[mi][ni], aF[0][mi], bF[1][ni]);
            #pragma unroll
            for (int mi = 0; mi < 4; mi++)
                #pragma unroll
                for (int ni = 0; ni < 4; ni++)
                    mma_bf16(acc[mi][ni], aF[1][mi], bF[0][ni]);
        }
    }

    // ---- epilogue: fp32 stores ----
    float* Cb = C + (size_t)b * MDIM * NDIM;
    #pragma unroll
    for (int mi = 0; mi < 4; mi++) {
        const int r = m0 + warp_m * 64 + mi * 16 + (lane >> 2);
        #pragma unroll
        for (int ni = 0; ni < 4; ni++) {
            const int cc = n0 + warp_n * 32 + ni * 8 + (lane & 3) * 2;
            *(float2*)&Cb[(size_t)r       * NDIM + cc] = make_float2(acc[mi][ni][0], acc[mi][ni][1]);
            *(float2*)&Cb[(size_t)(r + 8) * NDIM + cc] = make_float2(acc[mi][ni][2], acc[mi][ni][3]);
        }
    }
}

// ---------------------------------------------------------------------------
// Softmax over rows of g_scores (V=1024), output split into P hi/lo.
// ---------------------------------------------------------------------------
__global__ __launch_bounds__(256)
void softmax_split()
{
    const float* p = g_scores + (size_t)blockIdx.x * NDIM;
    const int tid  = threadIdx.x;
    const int lane = tid & 31;
    const int wid  = tid >> 5;

    __shared__ float red_max[8];
    __shared__ float red_sum[8];

    float4 v = ((const float4*)p)[tid];

    float m = fmaxf(fmaxf(v.x, v.y), fmaxf(v.z, v.w));
    #pragma unroll
    for (int o = 16; o > 0; o >>= 1) m = fmaxf(m, __shfl_xor_sync(0xFFFFFFFFu, m, o));
    if (lane == 0) red_max[wid] = m;
    __syncthreads();
    float bmax = red_max[0];
    #pragma unroll
    for (int i = 1; i < 8; i++) bmax = fmaxf(bmax, red_max[i]);

    v.x = __expf(v.x - bmax);
    v.y = __expf(v.y - bmax);
    v.z = __expf(v.z - bmax);
    v.w = __expf(v.w - bmax);

    float s = v.x + v.y + v.z + v.w;
    #pragma unroll
    for (int o = 16; o > 0; o >>= 1) s += __shfl_xor_sync(0xFFFFFFFFu, s, o);
    if (lane == 0) red_sum[wid] = s;
    __syncthreads();
    float tot = 0.f;
    #pragma unroll
    for (int i = 0; i < 8; i++) tot += red_sum[i];
    const float inv = __frcp_rn(tot);

    v.x *= inv; v.y *= inv; v.z *= inv; v.w *= inv;

    bf16 h0 = __float2bfloat16(v.x), h1 = __float2bfloat16(v.y);
    bf16 h2 = __float2bfloat16(v.z), h3 = __float2bfloat16(v.w);
    bf16 l0 = __float2bfloat16(v.x - __bfloat162float(h0));
    bf16 l1 = __float2bfloat16(v.y - __bfloat162float(h1));
    bf16 l2 = __float2bfloat16(v.z - __bfloat162float(h2));
    bf16 l3 = __float2bfloat16(v.w - __bfloat162float(h3));

    bf162 hp0(h0, h1), hp1(h2, h3), lp0(l0, l1), lp1(l2, l3);
    const size_t i4 = (size_t)blockIdx.x * (NDIM / 4) + tid;    // uint2 index
    ((uint2*)g_Ph)[i4] = make_uint2(*(uint32_t*)&hp0, *(uint32_t*)&hp1);
    ((uint2*)g_Pl)[i4] = make_uint2(*(uint32_t*)&lp0, *(uint32_t*)&lp1);
}

// ---------------------------------------------------------------------------
extern "C" void kernel_launch(void* const* d_in, const int* in_sizes, int n_in,
                              void* d_out, int out_size)
{
    const float* H  = (const float*)d_in[0];   // (8, 2048, 1024)
    const float* Vx = (const float*)d_in[1];   // (8, 1024, 1024)
    float*       O  = (float*)d_out;           // (8, 2048, 1024)

    cudaFuncSetAttribute(gemm_split, cudaFuncAttributeMaxDynamicSharedMemorySize, SMEM_BYTES);

    convert_all<<<V_BLOCKS + H_BLOCKS, 1024>>>(H, Vx);

    dim3 g(NDIM / 128, MDIM / 128, BATCH);     // (8, 16, 8)
    gemm_split<<<g, 256, SMEM_BYTES>>>(0, O);  // scores = H @ V^T

    softmax_split<<<BATCH * MDIM, 256>>>();    // P -> hi/lo

    gemm_split<<<g, 256, SMEM_BYTES>>>(1, O);  // out = P @ V (via VT)
}

// round 12
// speedup vs baseline: 1.1635x; 1.0202x over previous
#include <cuda_runtime.h>
#include <cuda_bf16.h>
#include <cstdint>

using bf16  = __nv_bfloat16;
using bf162 = __nv_bfloat162;

// Problem dims: B=8, L=2048, V=1024, D=1024, fp32.
// Both GEMMs: M=2048, N=1024, K=1024 per batch, NT form (both operands K-major).
#define BATCH 8
#define MDIM  2048
#define NDIM  1024
#define KDIM  1024

// ---------------------------------------------------------------------------
// Device scratch (allocation-free rule: __device__ globals)
// ---------------------------------------------------------------------------
__device__ float g_scores[(size_t)BATCH * MDIM * NDIM];   // 64 MB
__device__ bf16  g_Hh [(size_t)BATCH * MDIM * KDIM];      // 32 MB each
__device__ bf16  g_Hl [(size_t)BATCH * MDIM * KDIM];
__device__ bf16  g_Ph [(size_t)BATCH * MDIM * KDIM];
__device__ bf16  g_Pl [(size_t)BATCH * MDIM * KDIM];
__device__ bf16  g_Vbh[(size_t)BATCH * NDIM * KDIM];      // 16 MB each
__device__ bf16  g_Vbl[(size_t)BATCH * NDIM * KDIM];
__device__ bf16  g_VTh[(size_t)BATCH * NDIM * KDIM];      // V transposed
__device__ bf16  g_VTl[(size_t)BATCH * NDIM * KDIM];

// ---------------------------------------------------------------------------
// PTX helpers (baseline sm_80+ features: cp.async, ldmatrix, mma.sync)
// ---------------------------------------------------------------------------
__device__ __forceinline__ uint32_t smem_u32(const void* p) {
    uint32_t a;
    asm("{ .reg .u64 t; cvta.to.shared.u64 t, %1; cvt.u32.u64 %0, t; }" : "=r"(a) : "l"(p));
    return a;
}
#define CP16(dst, src) \
    asm volatile("cp.async.cg.shared.global [%0], [%1], 16;" :: "r"(dst), "l"(src))
#define CP_COMMIT() asm volatile("cp.async.commit_group;" ::: "memory")
#define CP_WAIT1()  asm volatile("cp.async.wait_group 1;"  ::: "memory")

#define LDSM4(R, addr) \
    asm volatile("ldmatrix.sync.aligned.m8n8.x4.shared.b16 {%0,%1,%2,%3}, [%4];" \
        : "=r"((R)[0]), "=r"((R)[1]), "=r"((R)[2]), "=r"((R)[3]) : "r"(addr))

__device__ __forceinline__ void mma_bf16(float* c, const uint32_t* a, const uint32_t* b) {
    asm volatile(
        "mma.sync.aligned.m16n8k16.row.col.f32.bf16.bf16.f32 "
        "{%0,%1,%2,%3}, {%4,%5,%6,%7}, {%8,%9}, {%0,%1,%2,%3};"
        : "+f"(c[0]), "+f"(c[1]), "+f"(c[2]), "+f"(c[3])
        : "r"(a[0]), "r"(a[1]), "r"(a[2]), "r"(a[3]), "r"(b[0]), "r"(b[1]));
}

// ---------------------------------------------------------------------------
// Merged split-conversion kernel (same as R11 winner).
// ---------------------------------------------------------------------------
#define V_BLOCKS 8192                          // 8 batches * 32 * 32
#define H_BLOCKS 2048                          // 16.78M floats / (1024 thr * 8)

__global__ __launch_bounds__(1024)
void convert_all(const float* __restrict__ H, const float* __restrict__ Vx)
{
    const int bid = blockIdx.x;
    if (bid < V_BLOCKS) {
        __shared__ float tile[32][33];
        const int b   = bid >> 10;
        const int rem = bid & 1023;
        const int by  = rem >> 5;
        const int bx  = rem & 31;
        const int tx  = threadIdx.x & 31;
        const int ty  = threadIdx.x >> 5;
        const size_t base = (size_t)b * NDIM * KDIM;

        const int x = bx * 32 + tx;
        const int y = by * 32 + ty;
        float v = Vx[base + (size_t)y * 1024 + x];
        bf16 h = __float2bfloat16(v);
        bf16 l = __float2bfloat16(v - __bfloat162float(h));
        g_Vbh[base + (size_t)y * 1024 + x] = h;
        g_Vbl[base + (size_t)y * 1024 + x] = l;

        tile[ty][tx] = v;
        __syncthreads();

        const int xt = by * 32 + tx;
        const int yt = bx * 32 + ty;
        float tv = tile[tx][ty];
        bf16 th = __float2bfloat16(tv);
        bf16 tl = __float2bfloat16(tv - __bfloat162float(th));
        g_VTh[base + (size_t)yt * 1024 + xt] = th;
        g_VTl[base + (size_t)yt * 1024 + xt] = tl;
    } else {
        const size_t i = (size_t)(bid - V_BLOCKS) * 1024 + threadIdx.x;
        float4 v0 = ((const float4*)H)[2 * i];
        float4 v1 = ((const float4*)H)[2 * i + 1];
        const float f[8] = {v0.x, v0.y, v0.z, v0.w, v1.x, v1.y, v1.z, v1.w};
        uint32_t hw[4], lw[4];
        #pragma unroll
        for (int q = 0; q < 4; q++) {
            bf16 ha = __float2bfloat16(f[2*q]);
            bf16 hb = __float2bfloat16(f[2*q + 1]);
            bf16 la = __float2bfloat16(f[2*q]     - __bfloat162float(ha));
            bf16 lb = __float2bfloat16(f[2*q + 1] - __bfloat162float(hb));
            bf162 hp(ha, hb), lp(la, lb);
            hw[q] = *(uint32_t*)&hp;
            lw[q] = *(uint32_t*)&lp;
        }
        ((uint4*)g_Hh)[i] = make_uint4(hw[0], hw[1], hw[2], hw[3]);
        ((uint4*)g_Hl)[i] = make_uint4(lw[0], lw[1], lw[2], lw[3]);
    }
}

// ---------------------------------------------------------------------------
// Split-bf16 mma.sync GEMM (NT): C[m,n] = sum_k A[m,k]*B[n,k]
// CTA tile 128x128, BK=64, 8 warps (2 in M x 4 in N), warp tile 64x32.
// 3-stage cp.async pipeline; cp.async issue interleaved into compute blocks;
// ldmatrix fragments double-buffered across k16 blocks.
// ---------------------------------------------------------------------------
#define TILE_BYTES  16384                    // 128 rows * 128 B
#define STAGE_BYTES (4 * TILE_BYTES)         // 65536
#define NSTAGE      3
#define SMEM_BYTES  (NSTAGE * STAGE_BYTES)   // 196608

// byte offset of 16B atom (row, chunk) inside a tile, XOR swizzled
#define SWZ(row, ch) ((uint32_t)((row) * 128 + (((ch) ^ ((row) & 7)) << 4)))

__global__ void __launch_bounds__(256, 1)
gemm_split(int mode, float* __restrict__ Out)
{
    extern __shared__ char smem[];
    const uint32_t smb = smem_u32(smem);

    const int tid  = threadIdx.x;
    const int wid  = tid >> 5;
    const int lane = tid & 31;
    const int warp_m = wid >> 2;     // 0..1
    const int warp_n = wid & 3;      // 0..3

    const int b  = blockIdx.z;
    const int m0 = blockIdx.y * 128;
    const int n0 = blockIdx.x * 128;

    const bf16 *Ah, *Al, *Bh, *Bl;
    float* C;
    if (mode == 0) { Ah = g_Hh; Al = g_Hl; Bh = g_Vbh; Bl = g_Vbl; C = g_scores; }
    else           { Ah = g_Ph; Al = g_Pl; Bh = g_VTh; Bl = g_VTl; C = Out;      }

    const bf16* Ahp = Ah + (size_t)b * MDIM * KDIM + (size_t)m0 * KDIM;
    const bf16* Alp = Al + (size_t)b * MDIM * KDIM + (size_t)m0 * KDIM;
    const bf16* Bhp = Bh + (size_t)b * NDIM * KDIM + (size_t)n0 * KDIM;
    const bf16* Blp = Bl + (size_t)b * NDIM * KDIM + (size_t)n0 * KDIM;

    // issue one quarter (4 CP16 per thread) of a stage's loads
    auto issue_chunk = [&](int s, int kt, int i) {
        const int ke = kt * 64;
        const uint32_t sbase = smb + s * STAGE_BYTES;
        const int c   = tid + i * 256;    // 0..1023
        const int row = c >> 3;           // 0..127
        const int ch  = c & 7;            // 16B chunk within 128B row
        const uint32_t dst = sbase + SWZ(row, ch);
        const size_t  goff = (size_t)row * KDIM + ke + ch * 8;
        CP16(dst + 0 * TILE_BYTES, Ahp + goff);
        CP16(dst + 1 * TILE_BYTES, Alp + goff);
        CP16(dst + 2 * TILE_BYTES, Bhp + goff);
        CP16(dst + 3 * TILE_BYTES, Blp + goff);
    };
    auto load_stage = [&](int s, int kt) {
        #pragma unroll
        for (int i = 0; i < 4; i++) issue_chunk(s, kt, i);
    };

    // fragment addressing (constant per thread)
    const int arow = warp_m * 64 + (lane & 15);
    const int asel = (lane >> 4);                          // chunk offset 0/1
    const int brow = warp_n * 32 + (lane & 7) + ((lane >> 4) & 1) * 8;
    const int bsel = ((lane >> 3) & 1);

    // fragment buffers: [buf][hi/lo][tile][reg]
    uint32_t aF[2][2][4][4];
    uint32_t bF[2][2][4][2];

    auto load_frags = [&](int buf, uint32_t sb, int ks) {
        const int kch = ks * 2;
        #pragma unroll
        for (int mi = 0; mi < 4; mi++) {
            const uint32_t addr = sb + SWZ(arow + mi * 16, kch + asel);
            LDSM4(aF[buf][0][mi], addr + 0 * TILE_BYTES);
            LDSM4(aF[buf][1][mi], addr + 1 * TILE_BYTES);
        }
        #pragma unroll
        for (int np = 0; np < 2; np++) {
            const uint32_t addr = sb + 2 * TILE_BYTES + SWZ(brow + np * 16, kch + bsel);
            uint32_t r4[4];
            LDSM4(r4, addr);
            bF[buf][0][np*2][0]   = r4[0]; bF[buf][0][np*2][1]   = r4[1];
            bF[buf][0][np*2+1][0] = r4[2]; bF[buf][0][np*2+1][1] = r4[3];
            LDSM4(r4, addr + TILE_BYTES);
            bF[buf][1][np*2][0]   = r4[0]; bF[buf][1][np*2][1]   = r4[1];
            bF[buf][1][np*2+1][0] = r4[2]; bF[buf][1][np*2+1][1] = r4[3];
        }
    };

    float acc[4][4][4];
    #pragma unroll
    for (int mi = 0; mi < 4; mi++)
        #pragma unroll
        for (int ni = 0; ni < 4; ni++)
            #pragma unroll
            for (int r = 0; r < 4; r++) acc[mi][ni][r] = 0.f;

    load_stage(0, 0); CP_COMMIT();
    load_stage(1, 1); CP_COMMIT();

    const int NKT = KDIM / 64;  // 16
    for (int kt = 0; kt < NKT; kt++) {
        CP_WAIT1();              // stage kt's group complete (<=1 pending)
        __syncthreads();         // all warps done reading stage (kt+2)%3

        const uint32_t sb = smb + (kt % NSTAGE) * STAGE_BYTES;
        const bool prefetch = (kt + 2 < NKT);
        const int  ps = (kt + 2) % NSTAGE;

        load_frags(0, sb, 0);    // prime fragment pipeline

        #pragma unroll
        for (int ks = 0; ks < 4; ks++) {
            const int cur = ks & 1;
            // interleave next-stage global loads into the compute blocks
            if (prefetch) issue_chunk(ps, kt + 2, ks);
            // prefetch next k16 block's fragments
            if (ks < 3) load_frags((ks + 1) & 1, sb, ks + 1);
            // 3 split passes over the 16 (mi,ni) tiles with cur fragments
            #pragma unroll
            for (int mi = 0; mi < 4; mi++)
                #pragma unroll
                for (int ni = 0; ni < 4; ni++)
                    mma_bf16(acc[mi][ni], aF[cur][0][mi], bF[cur][0][ni]);
            #pragma unroll
            for (int mi = 0; mi < 4; mi++)
                #pragma unroll
                for (int ni = 0; ni < 4; ni++)
                    mma_bf16(acc[mi][ni], aF[cur][0][mi], bF[cur][1][ni]);
            #pragma unroll
            for (int mi = 0; mi < 4; mi++)
                #pragma unroll
                for (int ni = 0; ni < 4; ni++)
                    mma_bf16(acc[mi][ni], aF[cur][1][mi], bF[cur][0][ni]);
        }
        CP_COMMIT();
    }

    // ---- epilogue: fp32 stores ----
    float* Cb = C + (size_t)b * MDIM * NDIM;
    #pragma unroll
    for (int mi = 0; mi < 4; mi++) {
        const int r = m0 + warp_m * 64 + mi * 16 + (lane >> 2);
        #pragma unroll
        for (int ni = 0; ni < 4; ni++) {
            const int cc = n0 + warp_n * 32 + ni * 8 + (lane & 3) * 2;
            *(float2*)&Cb[(size_t)r       * NDIM + cc] = make_float2(acc[mi][ni][0], acc[mi][ni][1]);
            *(float2*)&Cb[(size_t)(r + 8) * NDIM + cc] = make_float2(acc[mi][ni][2], acc[mi][ni][3]);
        }
    }
}

// ---------------------------------------------------------------------------
// Softmax over rows of g_scores (V=1024), output split into P hi/lo.
// ---------------------------------------------------------------------------
__global__ __launch_bounds__(256)
void softmax_split()
{
    const float* p = g_scores + (size_t)blockIdx.x * NDIM;
    const int tid  = threadIdx.x;
    const int lane = tid & 31;
    const int wid  = tid >> 5;

    __shared__ float red_max[8];
    __shared__ float red_sum[8];

    float4 v = ((const float4*)p)[tid];

    float m = fmaxf(fmaxf(v.x, v.y), fmaxf(v.z, v.w));
    #pragma unroll
    for (int o = 16; o > 0; o >>= 1) m = fmaxf(m, __shfl_xor_sync(0xFFFFFFFFu, m, o));
    if (lane == 0) red_max[wid] = m;
    __syncthreads();
    float bmax = red_max[0];
    #pragma unroll
    for (int i = 1; i < 8; i++) bmax = fmaxf(bmax, red_max[i]);

    v.x = __expf(v.x - bmax);
    v.y = __expf(v.y - bmax);
    v.z = __expf(v.z - bmax);
    v.w = __expf(v.w - bmax);

    float s = v.x + v.y + v.z + v.w;
    #pragma unroll
    for (int o = 16; o > 0; o >>= 1) s += __shfl_xor_sync(0xFFFFFFFFu, s, o);
    if (lane == 0) red_sum[wid] = s;
    __syncthreads();
    float tot = 0.f;
    #pragma unroll
    for (int i = 0; i < 8; i++) tot += red_sum[i];
    const float inv = __frcp_rn(tot);

    v.x *= inv; v.y *= inv; v.z *= inv; v.w *= inv;

    bf16 h0 = __float2bfloat16(v.x), h1 = __float2bfloat16(v.y);
    bf16 h2 = __float2bfloat16(v.z), h3 = __float2bfloat16(v.w);
    bf16 l0 = __float2bfloat16(v.x - __bfloat162float(h0));
    bf16 l1 = __float2bfloat16(v.y - __bfloat162float(h1));
    bf16 l2 = __float2bfloat16(v.z - __bfloat162float(h2));
    bf16 l3 = __float2bfloat16(v.w - __bfloat162float(h3));

    bf162 hp0(h0, h1), hp1(h2, h3), lp0(l0, l1), lp1(l2, l3);
    const size_t i4 = (size_t)blockIdx.x * (NDIM / 4) + tid;    // uint2 index
    ((uint2*)g_Ph)[i4] = make_uint2(*(uint32_t*)&hp0, *(uint32_t*)&hp1);
    ((uint2*)g_Pl)[i4] = make_uint2(*(uint32_t*)&lp0, *(uint32_t*)&lp1);
}

// ---------------------------------------------------------------------------
extern "C" void kernel_launch(void* const* d_in, const int* in_sizes, int n_in,
                              void* d_out, int out_size)
{
    const float* H  = (const float*)d_in[0];   // (8, 2048, 1024)
    const float* Vx = (const float*)d_in[1];   // (8, 1024, 1024)
    float*       O  = (float*)d_out;           // (8, 2048, 1024)

    cudaFuncSetAttribute(gemm_split, cudaFuncAttributeMaxDynamicSharedMemorySize, SMEM_BYTES);

    convert_all<<<V_BLOCKS + H_BLOCKS, 1024>>>(H, Vx);

    dim3 g(NDIM / 128, MDIM / 128, BATCH);     // (8, 16, 8)
    gemm_split<<<g, 256, SMEM_BYTES>>>(0, O);  // scores = H @ V^T

    softmax_split<<<BATCH * MDIM, 256>>>();    // P -> hi/lo

    gemm_split<<<g, 256, SMEM_BYTES>>>(1, O);  // out = P @ V (via VT)
}